// round 15
// baseline (speedup 1.0000x reference)
#include <cuda_runtime.h>
#include <cuda_fp16.h>

// Problem constants: B=2048, T=512, I=4, H=64, O=4
#define TT 512
#define BB 2048
#define HH 64
#define OO 4
#define NB 16    // batch rows per block = mma M tile (exact: 2048 = 128*16)
#define GRID 128
#define NT 512   // 16 warps; warp w owns hidden units [4w, 4w+4)
#define HW 88    // A row width in halfs: 0-63 h, 64-67 x, 68 bias-one, 69-87 zero

__device__ __forceinline__ float tanh_ap(float x){
    float r; asm("tanh.approx.f32 %0, %1;" : "=f"(r) : "f"(x)); return r;
}
__device__ __forceinline__ float sig_ap(float x){
    return __fmaf_rn(0.5f, tanh_ap(0.5f * x), 0.5f);
}
__device__ __forceinline__ unsigned packh2(float lo, float hi){
    __half2 h = __floats2half2_rn(lo, hi);
    return *reinterpret_cast<unsigned*>(&h);
}
// D = A(16x16 f16, row) * B(16x8 f16, col) + D (f32)
__device__ __forceinline__ void mma16816(float* c, const unsigned* a, unsigned b0, unsigned b1){
    asm volatile(
        "mma.sync.aligned.m16n8k16.row.col.f32.f16.f16.f32 "
        "{%0,%1,%2,%3}, {%4,%5,%6,%7}, {%8,%9}, {%0,%1,%2,%3};\n"
        : "+f"(c[0]), "+f"(c[1]), "+f"(c[2]), "+f"(c[3])
        : "r"(a[0]), "r"(a[1]), "r"(a[2]), "r"(a[3]), "r"(b0), "r"(b1));
}
__device__ __forceinline__ void ldsm_x4(unsigned &r0, unsigned &r1, unsigned &r2, unsigned &r3,
                                        unsigned addr){
    asm volatile("ldmatrix.sync.aligned.m8n8.x4.shared.b16 {%0,%1,%2,%3}, [%4];"
                 : "=r"(r0), "=r"(r1), "=r"(r2), "=r"(r3) : "r"(addr));
}
__device__ __forceinline__ unsigned smem_u32(const void* p){
    return (unsigned)__cvta_generic_to_shared(p);
}

__global__ void __launch_bounds__(NT, 1) lstm_mma_kernel(
    const float* __restrict__ x,     // [B, T, I]
    const float* __restrict__ W_ih,  // [4H, I]
    const float* __restrict__ W_hh,  // [4H, H]
    const float* __restrict__ b_ih,  // [4H]
    const float* __restrict__ b_hh,  // [4H]
    const float* __restrict__ W_fc,  // [O, H]
    const float* __restrict__ b_fc,  // [O]
    float* __restrict__ out)         // [1, B, O]
{
    __shared__ __half h_sh[2][NB][HW];   // double-buffered augmented A matrix (fp16)

    const int tid  = threadIdx.x;
    const int wid  = tid >> 5;           // 0..15
    const int lane = tid & 31;
    const int g    = lane >> 2;
    const int ti   = lane & 3;
    const int bbase = blockIdx.x * NB;

    // Per-warp 16 columns = 2 n-tiles covering units u = wid*4 + (n>>1):
    //   tile 0: col n = 2k -> gate i of unit, 2k+1 -> gate g
    //   tile 1: col n = 2k -> gate f,         2k+1 -> gate o
    // W row offsets: i:0, f:64, g:128, o:192.

    // ---- B fragments (stationary weights): [nt 0..1][kt 0..4] ----
    unsigned bf0[2][5], bf1[2][5];
    #pragma unroll
    for (int nt = 0; nt < 2; nt++){
        int n  = g;                                  // fragment n index = lane>>2
        int u  = wid*4 + (n >> 1);
        int gate = nt ? ((n & 1) ? 3 : 1)            // tile 1: f / o
                      : ((n & 1) ? 2 : 0);           // tile 0: i / g
        int wrow = u + (gate == 0 ? 0 : gate == 1 ? 64 : gate == 2 ? 128 : 192);
        #pragma unroll
        for (int kt = 0; kt < 4; kt++){
            const float* wr = W_hh + (size_t)wrow * HH + kt*16;
            bf0[nt][kt] = packh2(wr[2*ti],     wr[2*ti + 1]);
            bf1[nt][kt] = packh2(wr[2*ti + 8], wr[2*ti + 9]);
        }
        // kt=4: k rows 64-67 = W_ih, 68 = bias, rest 0
        float e0 = 0.f, e1 = 0.f;
        if (ti < 2){ e0 = W_ih[wrow*4 + 2*ti]; e1 = W_ih[wrow*4 + 2*ti + 1]; }
        else if (ti == 2){ e0 = b_ih[wrow] + b_hh[wrow]; }
        bf0[nt][4] = packh2(e0, e1);
        bf1[nt][4] = 0u;
    }

    // ---- ldmatrix per-lane source offsets ----
    const int lrow = (lane & 7) + ((lane >> 3) & 1) * 8;
    const int lcol = (lane >> 4) << 3;
    const unsigned abase0 = smem_u32(&h_sh[0][lrow][lcol]);
    const unsigned abase1 = smem_u32(&h_sh[1][lrow][lcol]);

    // ---- init shared: zero both buffers, bias-one col, x(t=0) ----
    for (int i = tid; i < 2*NB*HW; i += NT) ((__half*)h_sh)[i] = __float2half(0.f);
    __syncthreads();
    if (tid < 2*NB){
        int p = tid >> 4, r = tid & 15;
        h_sh[p][r][68] = __float2half(1.f);
    }
    if (tid < NB){
        float4 xv = ((const float4*)x)[ (size_t)(bbase + tid) * TT ];
        h_sh[0][tid][64] = __float2half(xv.x);
        h_sh[0][tid][65] = __float2half(xv.y);
        h_sh[0][tid][66] = __float2half(xv.z);
        h_sh[0][tid][67] = __float2half(xv.w);
    }
    __syncthreads();

    // cell state: cc[s] = c for unit (wid*4 + ti), batch row (s ? g+8 : g)
    float cc0 = 0.f, cc1 = 0.f;
    const int uown = wid*4 + ti;

    for (int t = 0; t < TT; t++){
        const int p = t & 1;
        const unsigned abase = p ? abase1 : abase0;

        // prefetch next x
        float4 xn;
        const bool pre = (tid < NB) && (t + 1 < TT);
        if (pre) xn = ((const float4*)x)[ (size_t)(bbase + tid) * TT + (t + 1) ];

        // ---- A fragments via ldmatrix.x4 ----
        unsigned af[5][4];
        #pragma unroll
        for (int kt = 0; kt < 5; kt++)
            ldsm_x4(af[kt][0], af[kt][1], af[kt][2], af[kt][3], abase + kt*32);

        // ---- gates = [h | x | 1] @ Waug^T (fp32 accum, 2 independent chains) ----
        float C[2][4];
        C[0][0] = 0.f; C[0][1] = 0.f; C[0][2] = 0.f; C[0][3] = 0.f;
        C[1][0] = 0.f; C[1][1] = 0.f; C[1][2] = 0.f; C[1][3] = 0.f;
        #pragma unroll
        for (int kt = 0; kt < 5; kt++){
            mma16816(C[0], af[kt], bf0[0][kt], bf1[0][kt]);
            mma16816(C[1], af[kt], bf0[1][kt], bf1[1][kt]);
        }

        // ---- epilogue: all 4 gates of a unit on THIS lane (no shfl) ----
        {
            // s = 0 (batch row g)
            {
                float ai = sig_ap(C[0][0]);
                float ag = tanh_ap(C[0][1]);
                float af_ = sig_ap(C[1][0]);
                float ao = sig_ap(C[1][1]);
                cc0 = __fmaf_rn(af_, cc0, ai * ag);
                h_sh[p ^ 1][g][uown] = __float2half(ao * tanh_ap(cc0));
            }
            // s = 1 (batch row g+8)
            {
                float ai = sig_ap(C[0][2]);
                float ag = tanh_ap(C[0][3]);
                float af_ = sig_ap(C[1][2]);
                float ao = sig_ap(C[1][3]);
                cc1 = __fmaf_rn(af_, cc1, ai * ag);
                h_sh[p ^ 1][g + 8][uown] = __float2half(ao * tanh_ap(cc1));
            }
        }

        // stage next x into the buffer being written this step
        if (pre){
            h_sh[p ^ 1][tid][64] = __float2half(xn.x);
            h_sh[p ^ 1][tid][65] = __float2half(xn.y);
            h_sh[p ^ 1][tid][66] = __float2half(xn.z);
            h_sh[p ^ 1][tid][67] = __float2half(xn.w);
        }
        __syncthreads();
    }

    // ---- FC head: final h in buffer 0 (TT even) ----
    if (tid < NB * OO){
        const int b = tid >> 2, o = tid & 3;
        float s = b_fc[o];
        #pragma unroll
        for (int k = 0; k < HH; k++)
            s = __fmaf_rn(W_fc[o*HH + k], __half2float(h_sh[0][b][k]), s);
        out[(size_t)(bbase + b) * OO + o] = s;
    }
}

extern "C" void kernel_launch(void* const* d_in, const int* in_sizes, int n_in,
                              void* d_out, int out_size)
{
    const float* x    = (const float*)d_in[0];
    const float* W_ih = (const float*)d_in[1];
    const float* W_hh = (const float*)d_in[2];
    const float* b_ih = (const float*)d_in[3];
    const float* b_hh = (const float*)d_in[4];
    const float* W_fc = (const float*)d_in[5];
    const float* b_fc = (const float*)d_in[6];
    float* out = (float*)d_out;

    lstm_mma_kernel<<<GRID, NT>>>(x, W_ih, W_hh, b_ih, b_hh, W_fc, b_fc, out);
}

// round 17
// speedup vs baseline: 1.5965x; 1.5965x over previous
#include <cuda_runtime.h>
#include <cuda_fp16.h>

// Problem constants: B=2048, T=512, I=4, H=64, O=4
#define TT 512
#define BB 2048
#define HH 64
#define OO 4
#define NB 16    // batch rows per block = mma M tile (exact: 2048 = 128*16)
#define GRID 128
#define NT 256   // 8 warps; warp w owns hidden units [8w, 8w+8)
#define HW 88    // A row width in halfs: 0-63 h, 64-67 x, 68 bias-one, 69-87 zero

__device__ __forceinline__ unsigned packh2(float lo, float hi){
    __half2 h = __floats2half2_rn(lo, hi);
    return *reinterpret_cast<unsigned*>(&h);
}
__device__ __forceinline__ __half2 h2tanh_ap(__half2 v){
    __half2 r;
    asm("tanh.approx.f16x2 %0, %1;"
        : "=r"(*reinterpret_cast<unsigned*>(&r))
        : "r"(*reinterpret_cast<const unsigned*>(&v)));
    return r;
}
// D = A(16x16 f16, row) * B(16x8 f16, col) + D (f32)
__device__ __forceinline__ void mma16816(float* c, const unsigned* a, unsigned b0, unsigned b1){
    asm volatile(
        "mma.sync.aligned.m16n8k16.row.col.f32.f16.f16.f32 "
        "{%0,%1,%2,%3}, {%4,%5,%6,%7}, {%8,%9}, {%0,%1,%2,%3};\n"
        : "+f"(c[0]), "+f"(c[1]), "+f"(c[2]), "+f"(c[3])
        : "r"(a[0]), "r"(a[1]), "r"(a[2]), "r"(a[3]), "r"(b0), "r"(b1));
}
__device__ __forceinline__ void ldsm_x4(unsigned &r0, unsigned &r1, unsigned &r2, unsigned &r3,
                                        unsigned addr){
    asm volatile("ldmatrix.sync.aligned.m8n8.x4.shared.b16 {%0,%1,%2,%3}, [%4];"
                 : "=r"(r0), "=r"(r1), "=r"(r2), "=r"(r3) : "r"(addr));
}
__device__ __forceinline__ unsigned smem_u32(const void* p){
    return (unsigned)__cvta_generic_to_shared(p);
}

__global__ void __launch_bounds__(NT, 1) lstm_mma_kernel(
    const float* __restrict__ x,     // [B, T, I]
    const float* __restrict__ W_ih,  // [4H, I]
    const float* __restrict__ W_hh,  // [4H, H]
    const float* __restrict__ b_ih,  // [4H]
    const float* __restrict__ b_hh,  // [4H]
    const float* __restrict__ W_fc,  // [O, H]
    const float* __restrict__ b_fc,  // [O]
    float* __restrict__ out)         // [1, B, O]
{
    __shared__ __half h_sh[2][NB][HW];   // double-buffered augmented A matrix (fp16)

    const int tid  = threadIdx.x;
    const int wid  = tid >> 5;           // 0..7
    const int lane = tid & 31;
    const int g    = lane >> 2;
    const int ti   = lane & 3;
    const int bbase = blockIdx.x * NB;

    // Gate-column permutation (per warp, 4 n-tiles = 32 cols):
    //   tile pair pp = nt>>1 covers units u = wid*8 + pp*4 + (n>>1)
    //   even tile: col n = 2k -> gate i, 2k+1 -> gate g
    //   odd  tile: col n = 2k -> gate f, 2k+1 -> gate o
    // W row offsets: i:0, f:64, g:128, o:192.

    // ---- B fragments (stationary weights): [nt 0..3][kt 0..4] ----
    unsigned bf0[4][5], bf1[4][5];
    #pragma unroll
    for (int nt = 0; nt < 4; nt++){
        int n  = g;
        int u  = wid*8 + (nt >> 1)*4 + (n >> 1);
        int gate = (nt & 1) ? ((n & 1) ? 3 : 1)      // odd tile: f / o
                            : ((n & 1) ? 2 : 0);     // even tile: i / g
        int wrow = u + (gate == 0 ? 0 : gate == 1 ? 64 : gate == 2 ? 128 : 192);
        #pragma unroll
        for (int kt = 0; kt < 4; kt++){
            const float* wr = W_hh + (size_t)wrow * HH + kt*16;
            bf0[nt][kt] = packh2(wr[2*ti],     wr[2*ti + 1]);
            bf1[nt][kt] = packh2(wr[2*ti + 8], wr[2*ti + 9]);
        }
        // kt=4: k rows 64-67 = W_ih, 68 = bias, rest 0
        float e0 = 0.f, e1 = 0.f;
        if (ti < 2){ e0 = W_ih[wrow*4 + 2*ti]; e1 = W_ih[wrow*4 + 2*ti + 1]; }
        else if (ti == 2){ e0 = b_ih[wrow] + b_hh[wrow]; }
        bf0[nt][4] = packh2(e0, e1);
        bf1[nt][4] = 0u;
    }

    // ---- ldmatrix per-lane source offsets ----
    const int lrow = (lane & 7) + ((lane >> 3) & 1) * 8;
    const int lcol = (lane >> 4) << 3;
    const unsigned abase0 = smem_u32(&h_sh[0][lrow][lcol]);
    const unsigned abase1 = smem_u32(&h_sh[1][lrow][lcol]);

    // ---- init shared: zero both buffers, bias-one col, x(t=0) ----
    for (int i = tid; i < 2*NB*HW; i += NT) ((__half*)h_sh)[i] = __float2half(0.f);
    __syncthreads();
    if (tid < 2*NB){
        int p = tid >> 4, r = tid & 15;
        h_sh[p][r][68] = __float2half(1.f);
    }
    if (tid < NB){
        float4 xv = ((const float4*)x)[ (size_t)(bbase + tid) * TT ];
        h_sh[0][tid][64] = __float2half(xv.x);
        h_sh[0][tid][65] = __float2half(xv.y);
        h_sh[0][tid][66] = __float2half(xv.z);
        h_sh[0][tid][67] = __float2half(xv.w);
    }
    __syncthreads();

    // cell state (fp32): cc[pp][s] for unit (wid*8 + pp*4 + ti), batch row (s ? g+8 : g)
    float cc[2][2];
    cc[0][0] = 0.f; cc[0][1] = 0.f; cc[1][0] = 0.f; cc[1][1] = 0.f;

    const __half2 h05 = __float2half2_rn(0.5f);

    for (int t = 0; t < TT; t++){
        const int p = t & 1;
        const unsigned abase = p ? abase1 : abase0;

        // prefetch next x
        float4 xn;
        const bool pre = (tid < NB) && (t + 1 < TT);
        if (pre) xn = ((const float4*)x)[ (size_t)(bbase + tid) * TT + (t + 1) ];

        // ---- A fragments via ldmatrix.x4 ----
        unsigned af[5][4];
        #pragma unroll
        for (int kt = 0; kt < 5; kt++)
            ldsm_x4(af[kt][0], af[kt][1], af[kt][2], af[kt][3], abase + kt*32);

        // ---- gates = [h | x | 1] @ Waug^T (fp32 accum, 4 independent chains) ----
        float C[4][4];
        #pragma unroll
        for (int nt = 0; nt < 4; nt++){
            C[nt][0] = 0.f; C[nt][1] = 0.f; C[nt][2] = 0.f; C[nt][3] = 0.f;
        }
        #pragma unroll
        for (int kt = 0; kt < 5; kt++){
            #pragma unroll
            for (int nt = 0; nt < 4; nt++)
                mma16816(C[nt], af[kt], bf0[nt][kt], bf1[nt][kt]);
        }

        // ---- epilogue: f16x2 activations over the (s0,s1) batch-row pair ----
        #pragma unroll
        for (int pp = 0; pp < 2; pp++){
            const int u = wid*8 + pp*4 + ti;
            __half2 vi2 = __floats2half2_rn(C[2*pp    ][0], C[2*pp    ][2]);
            __half2 vg2 = __floats2half2_rn(C[2*pp    ][1], C[2*pp    ][3]);
            __half2 vf2 = __floats2half2_rn(C[2*pp + 1][0], C[2*pp + 1][2]);
            __half2 vo2 = __floats2half2_rn(C[2*pp + 1][1], C[2*pp + 1][3]);

            __half2 ai2 = __hfma2(h05, h2tanh_ap(__hmul2(h05, vi2)), h05);  // sig(i)
            __half2 af2 = __hfma2(h05, h2tanh_ap(__hmul2(h05, vf2)), h05);  // sig(f)
            __half2 ao2 = __hfma2(h05, h2tanh_ap(__hmul2(h05, vo2)), h05);  // sig(o)
            __half2 ag2 = h2tanh_ap(vg2);                                   // tanh(g)

            __half2 ig2 = __hmul2(ai2, ag2);
            float2 igf = __half22float2(ig2);
            float2 aff = __half22float2(af2);
            cc[pp][0] = __fmaf_rn(aff.x, cc[pp][0], igf.x);   // fp32 integrator
            cc[pp][1] = __fmaf_rn(aff.y, cc[pp][1], igf.y);

            __half2 th2 = h2tanh_ap(__floats2half2_rn(cc[pp][0], cc[pp][1]));
            __half2 hv2 = __hmul2(ao2, th2);                  // sig(o)*tanh(c)
            h_sh[p ^ 1][g    ][u] = __low2half(hv2);
            h_sh[p ^ 1][g + 8][u] = __high2half(hv2);
        }

        // stage next x into the buffer being written this step
        if (pre){
            h_sh[p ^ 1][tid][64] = __float2half(xn.x);
            h_sh[p ^ 1][tid][65] = __float2half(xn.y);
            h_sh[p ^ 1][tid][66] = __float2half(xn.z);
            h_sh[p ^ 1][tid][67] = __float2half(xn.w);
        }
        __syncthreads();
    }

    // ---- FC head: final h in buffer 0 (TT even) ----
    if (tid < NB * OO){
        const int b = tid >> 2, o = tid & 3;
        float s = b_fc[o];
        #pragma unroll
        for (int k = 0; k < HH; k++)
            s = __fmaf_rn(W_fc[o*HH + k], __half2float(h_sh[0][b][k]), s);
        out[(size_t)(bbase + b) * OO + o] = s;
    }
}

extern "C" void kernel_launch(void* const* d_in, const int* in_sizes, int n_in,
                              void* d_out, int out_size)
{
    const float* x    = (const float*)d_in[0];
    const float* W_ih = (const float*)d_in[1];
    const float* W_hh = (const float*)d_in[2];
    const float* b_ih = (const float*)d_in[3];
    const float* b_hh = (const float*)d_in[4];
    const float* W_fc = (const float*)d_in[5];
    const float* b_fc = (const float*)d_in[6];
    float* out = (float*)d_out;

    lstm_mma_kernel<<<GRID, NT>>>(x, W_ih, W_hh, b_ih, b_hh, W_fc, b_fc, out);
}